// round 17
// baseline (speedup 1.0000x reference)
#include <cuda_runtime.h>
#include <cuda_fp16.h>
#include <cstdint>

#define N_NODES 40000
#define DIMF    128
#define N_EDGES 640000
#define CAP     96            // max supported in-degree (Poisson(16): P(>=96)~0)

// ---- scratch (no allocs allowed) ----
__device__ int    g_cur[N_NODES];           // sort cursors == degree after sort
__device__ int    g_esrc[N_NODES * CAP];    // src ids, padded CSR (15.4 MB)
__device__ __half g_mh[N_NODES * DIMF];     // fp16 neighbor-MEAN (GEMM A0)
__device__ __half g_xh[N_NODES * DIMF];     // fp16 shadow of x
__device__ __half g_hh[N_NODES * DIMF];     // fp16 shadow of h
__device__ __half g_wh[4 * DIMF * DIMF];    // fp16 weights: W1l, W1r, W2l, W2r

__device__ __forceinline__ uint32_t smem_u32(const void* p) {
    uint32_t a;
    asm("{ .reg .u64 t; cvta.to.shared.u64 t, %1; cvt.u32.u64 %0, t; }"
        : "=r"(a) : "l"(p));
    return a;
}

// ---------------------------------------------------------------------------
// prep: x -> fp16 shadow; zero cursors; convert 4 weight mats to fp16.
// ---------------------------------------------------------------------------
__global__ void prep_kernel(const float* __restrict__ x,
                            const float* __restrict__ w0,
                            const float* __restrict__ w1,
                            const float* __restrict__ w2,
                            const float* __restrict__ w3) {
    int i = blockIdx.x * blockDim.x + threadIdx.x;      // float4 index
    const int tot4 = N_NODES * DIMF / 4;
    if (i < tot4) {
        float4 v = reinterpret_cast<const float4*>(x)[i];
        __half2 h01 = __floats2half2_rn(v.x, v.y);
        __half2 h23 = __floats2half2_rn(v.z, v.w);
        uint2 packed;
        packed.x = *reinterpret_cast<uint32_t*>(&h01);
        packed.y = *reinterpret_cast<uint32_t*>(&h23);
        reinterpret_cast<uint2*>(g_xh)[i] = packed;
    }
    if (i < N_NODES) g_cur[i] = 0;
    const int per = DIMF * DIMF / 8;                    // 2048
    if (i < 4 * per) {
        const float* src = (i < per) ? w0 : (i < 2 * per) ? w1
                          : (i < 3 * per) ? w2 : w3;
        int rem = i & (per - 1);
        float4 a = reinterpret_cast<const float4*>(src)[rem * 2];
        float4 b = reinterpret_cast<const float4*>(src)[rem * 2 + 1];
        __half2 h0 = __floats2half2_rn(a.x, a.y), h1 = __floats2half2_rn(a.z, a.w);
        __half2 h2 = __floats2half2_rn(b.x, b.y), h3 = __floats2half2_rn(b.z, b.w);
        uint4 p;
        p.x = *reinterpret_cast<uint32_t*>(&h0);
        p.y = *reinterpret_cast<uint32_t*>(&h1);
        p.z = *reinterpret_cast<uint32_t*>(&h2);
        p.w = *reinterpret_cast<uint32_t*>(&h3);
        reinterpret_cast<uint4*>(g_wh)[i] = p;
    }
}

// ---------------------------------------------------------------------------
// padded-CSR counting sort: 4 edges/thread (MLP=4).
// ---------------------------------------------------------------------------
__global__ void sort_kernel(const int* __restrict__ ei) {
    int t  = blockIdx.x * blockDim.x + threadIdx.x;
    int e0 = t * 4;
    if (e0 >= N_EDGES) return;
    int4 s4 = *reinterpret_cast<const int4*>(ei + e0);
    int4 d4 = *reinterpret_cast<const int4*>(ei + N_EDGES + e0);
    int s[4] = {s4.x, s4.y, s4.z, s4.w};
    int d[4] = {d4.x, d4.y, d4.z, d4.w};
    int pos[4];
#pragma unroll
    for (int k = 0; k < 4; ++k)
        pos[k] = ((unsigned)d[k] < N_NODES) ? atomicAdd(&g_cur[d[k]], 1) : CAP;
#pragma unroll
    for (int k = 0; k < 4; ++k)
        if ((unsigned)s[k] < N_NODES && pos[k] < CAP)
            g_esrc[d[k] * CAP + pos[k]] = s[k];
}

// ---------------------------------------------------------------------------
// aggregate (gather): one warp per dst node; HADD2 tree per 8-row group.
// ---------------------------------------------------------------------------
__global__ __launch_bounds__(256) void agg_kernel(const __half* __restrict__ feat16) {
    const int w    = blockIdx.x * 8 + (threadIdx.x >> 5);
    const int lane = threadIdx.x & 31;
    if (w >= N_NODES) return;

    const int degc  = g_cur[w];
    const int deg   = min(degc, CAP);
    const int start = w * CAP;

    float4 acc = make_float4(0.f, 0.f, 0.f, 0.f);

    for (int base = 0; base < deg; base += 32) {
        const int n = min(32, deg - base);
        int idx = __ldg(&g_esrc[start + base + lane]);

        int j = 0;
        const int full = n & ~7;
#pragma unroll 1
        for (; j < full; j += 8) {
            int s0 = __shfl_sync(0xffffffffu, idx, j + 0);
            int s1 = __shfl_sync(0xffffffffu, idx, j + 1);
            int s2 = __shfl_sync(0xffffffffu, idx, j + 2);
            int s3 = __shfl_sync(0xffffffffu, idx, j + 3);
            int s4 = __shfl_sync(0xffffffffu, idx, j + 4);
            int s5 = __shfl_sync(0xffffffffu, idx, j + 5);
            int s6 = __shfl_sync(0xffffffffu, idx, j + 6);
            int s7 = __shfl_sync(0xffffffffu, idx, j + 7);
            uint2 r0 = reinterpret_cast<const uint2*>(feat16 + (size_t)s0 * DIMF)[lane];
            uint2 r1 = reinterpret_cast<const uint2*>(feat16 + (size_t)s1 * DIMF)[lane];
            uint2 r2 = reinterpret_cast<const uint2*>(feat16 + (size_t)s2 * DIMF)[lane];
            uint2 r3 = reinterpret_cast<const uint2*>(feat16 + (size_t)s3 * DIMF)[lane];
            uint2 r4 = reinterpret_cast<const uint2*>(feat16 + (size_t)s4 * DIMF)[lane];
            uint2 r5 = reinterpret_cast<const uint2*>(feat16 + (size_t)s5 * DIMF)[lane];
            uint2 r6 = reinterpret_cast<const uint2*>(feat16 + (size_t)s6 * DIMF)[lane];
            uint2 r7 = reinterpret_cast<const uint2*>(feat16 + (size_t)s7 * DIMF)[lane];
            __half2 lo = __hadd2(
                __hadd2(__hadd2(*reinterpret_cast<__half2*>(&r0.x),
                                *reinterpret_cast<__half2*>(&r1.x)),
                        __hadd2(*reinterpret_cast<__half2*>(&r2.x),
                                *reinterpret_cast<__half2*>(&r3.x))),
                __hadd2(__hadd2(*reinterpret_cast<__half2*>(&r4.x),
                                *reinterpret_cast<__half2*>(&r5.x)),
                        __hadd2(*reinterpret_cast<__half2*>(&r6.x),
                                *reinterpret_cast<__half2*>(&r7.x))));
            __half2 hi = __hadd2(
                __hadd2(__hadd2(*reinterpret_cast<__half2*>(&r0.y),
                                *reinterpret_cast<__half2*>(&r1.y)),
                        __hadd2(*reinterpret_cast<__half2*>(&r2.y),
                                *reinterpret_cast<__half2*>(&r3.y))),
                __hadd2(__hadd2(*reinterpret_cast<__half2*>(&r4.y),
                                *reinterpret_cast<__half2*>(&r5.y)),
                        __hadd2(*reinterpret_cast<__half2*>(&r6.y),
                                *reinterpret_cast<__half2*>(&r7.y))));
            float2 f01 = __half22float2(lo);
            float2 f23 = __half22float2(hi);
            acc.x += f01.x; acc.y += f01.y; acc.z += f23.x; acc.w += f23.y;
        }
#pragma unroll 1
        for (; j < n; ++j) {
            int s = __shfl_sync(0xffffffffu, idx, j);
            uint2 r = reinterpret_cast<const uint2*>(feat16 + (size_t)s * DIMF)[lane];
            float2 f01 = __half22float2(*reinterpret_cast<__half2*>(&r.x));
            float2 f23 = __half22float2(*reinterpret_cast<__half2*>(&r.y));
            acc.x += f01.x; acc.y += f01.y; acc.z += f23.x; acc.w += f23.y;
        }
    }

    const float inv = __frcp_rn(fmaxf((float)degc, 1.f));
    __half2 h01 = __floats2half2_rn(acc.x * inv, acc.y * inv);
    __half2 h23 = __floats2half2_rn(acc.z * inv, acc.w * inv);
    uint2 packed;
    packed.x = *reinterpret_cast<uint32_t*>(&h01);
    packed.y = *reinterpret_cast<uint32_t*>(&h23);
    reinterpret_cast<uint2*>(g_mh + (size_t)w * DIMF)[lane] = packed;
}

// ---------------------------------------------------------------------------
// fp16 tensor-core GEMM (m16n8k16) with LDSM fragment loads.
// Weights resident in smem; A staged two k-tiles/buffer; 8 syncs total.
// ---------------------------------------------------------------------------
#define BM   128
#define LDA2 40    // A pair-tile row stride (80B; 80=16*5, 5 coprime 8 -> LDSM ok)
#define LDB  136   // B row stride (272B; 16B*r mod 128 distinct -> LDSM ok)
#define SMEM_B_HALVES (2 * 128 * LDB)
#define SMEM_A_HALVES (2 * 128 * LDA2)
#define SMEM_BYTES ((SMEM_B_HALVES + SMEM_A_HALVES) * 2)

#define LDSM_X4(r0, r1, r2, r3, addr)                                          \
    asm volatile("ldmatrix.sync.aligned.m8n8.x4.shared.b16 {%0,%1,%2,%3}, [%4];" \
                 : "=r"(r0), "=r"(r1), "=r"(r2), "=r"(r3) : "r"(addr))

__global__ __launch_bounds__(256, 2) void gemm_tc_kernel(
        const __half* __restrict__ A0h, const __half* __restrict__ A1h,
        const __half* __restrict__ W0h, const __half* __restrict__ W1h,
        const float* __restrict__ bias, float* __restrict__ out,
        __half* out16) {
    extern __shared__ __half smem[];
    __half* Bw = smem;                     // [2][128][LDB]
    __half* As = smem + SMEM_B_HALVES;     // [2][128][LDA2]

    const int tid   = threadIdx.x;
    const int m0    = blockIdx.x * BM;
    const int lane  = tid & 31;
    const int warp  = tid >> 5;
    const int warpM = warp & 1;        // 0..1 -> 64 rows each
    const int warpN = warp >> 1;       // 0..3 -> 32 cols each
    const int lr    = lane >> 2;       // 0..7
    const int lc    = lane & 3;        // 0..3

    const int ar = tid >> 1;           // 0..127
    const int ac = (tid & 1) * 8;      // 0 or 8
    const int gar = m0 + ar;

    // LDSM lane addressing: row-sel = lane&15, col-sel = (lane>>4)*8 halves
    const int lrow = lane & 15;
    const int lcol = (lane >> 4) * 8;

    float acc[4][4][4];
#pragma unroll
    for (int i = 0; i < 4; ++i)
#pragma unroll
        for (int j = 0; j < 4; ++j)
#pragma unroll
            for (int f = 0; f < 4; ++f) acc[i][j][f] = 0.f;

    uint4 aP0, aP1;
    auto load_pair = [&](int p) {      // p = 0..7 (pairs of k-tiles)
        const __half* A = (p < 4) ? A0h : A1h;
        const int k0 = (p & 3) * 32 + ac;
        if (gar < N_NODES) {
            aP0 = *reinterpret_cast<const uint4*>(A + (size_t)gar * DIMF + k0);
            aP1 = *reinterpret_cast<const uint4*>(A + (size_t)gar * DIMF + k0 + 16);
        } else {
            aP0 = make_uint4(0u, 0u, 0u, 0u);
            aP1 = make_uint4(0u, 0u, 0u, 0u);
        }
    };
    auto store_pair = [&](int buf) {
        *reinterpret_cast<uint4*>(&As[buf * 128 * LDA2 + ar * LDA2 + ac])      = aP0;
        *reinterpret_cast<uint4*>(&As[buf * 128 * LDA2 + ar * LDA2 + 16 + ac]) = aP1;
    };

    // preload both weight matrices into smem (once)
#pragma unroll
    for (int op = 0; op < 2; ++op) {
        const __half* W = op ? W1h : W0h;
#pragma unroll
        for (int i = 0; i < 8; ++i) {
            int u   = tid + i * 256;        // 0..2047
            int row = u >> 4;
            int ch  = (u & 15) * 8;
            uint4 v = *reinterpret_cast<const uint4*>(W + row * DIMF + ch);
            *reinterpret_cast<uint4*>(&Bw[op * 128 * LDB + row * LDB + ch]) = v;
        }
    }
    load_pair(0);
    store_pair(0);
    __syncthreads();

    const uint32_t BwS = smem_u32(Bw);
    const uint32_t AsS = smem_u32(As);

#pragma unroll 1
    for (int p = 0; p < 8; ++p) {
        const int buf = p & 1;
        if (p < 7) load_pair(p + 1);       // deep prefetch hides under 32 MMAs

        const uint32_t BopS = BwS + (p < 4 ? 0 : 128 * LDB) * 2;
        const uint32_t AtS  = AsS + (buf * 128 * LDA2) * 2;

#pragma unroll
        for (int ph = 0; ph < 2; ++ph) {
            const int kb = (p & 3) * 32 + ph * 16;   // B k-offset (halves)
            const int ka = ph * 16;                  // A tile k-offset (halves)

            // B fragments: 2x LDSM.x4, each covers two n-tiles
            uint32_t bf0[4], bf1[4];
#pragma unroll
            for (int p2 = 0; p2 < 2; ++p2) {
                const int nb = warpN * 32 + p2 * 16;           // 16 n-rows
                uint32_t addr = BopS + ((nb + lrow) * LDB + kb + lcol) * 2;
                LDSM_X4(bf0[p2 * 2], bf0[p2 * 2 + 1],
                        bf1[p2 * 2], bf1[p2 * 2 + 1], addr);
            }
#pragma unroll
            for (int mt = 0; mt < 4; ++mt) {
                const int mb = warpM * 64 + mt * 16;
                uint32_t addr = AtS + ((mb + lrow) * LDA2 + ka + lcol) * 2;
                uint32_t a0, a1, a2, a3;
                LDSM_X4(a0, a1, a2, a3, addr);
#pragma unroll
                for (int nt = 0; nt < 4; ++nt) {
                    asm volatile(
                        "mma.sync.aligned.m16n8k16.row.col.f32.f16.f16.f32 "
                        "{%0,%1,%2,%3}, {%4,%5,%6,%7}, {%8,%9}, {%0,%1,%2,%3};"
                        : "+f"(acc[mt][nt][0]), "+f"(acc[mt][nt][1]),
                          "+f"(acc[mt][nt][2]), "+f"(acc[mt][nt][3])
                        : "r"(a0), "r"(a1), "r"(a2), "r"(a3),
                          "r"(bf0[nt]), "r"(bf1[nt]));
                }
            }
        }

        if (p < 7) {
            store_pair(buf ^ 1);
            __syncthreads();
        }
    }

    // epilogue: + bias, relu; fp32 out and/or fp16 shadow (each nullable)
#pragma unroll
    for (int nt = 0; nt < 4; ++nt) {
        const int n = warpN * 32 + nt * 8 + 2 * lc;
        const float bv0 = __ldg(&bias[n]);
        const float bv1 = __ldg(&bias[n + 1]);
#pragma unroll
        for (int mt = 0; mt < 4; ++mt) {
            const int r = m0 + warpM * 64 + mt * 16 + lr;
            if (r < N_NODES) {
                float vx = fmaxf(acc[mt][nt][0] + bv0, 0.f);
                float vy = fmaxf(acc[mt][nt][1] + bv1, 0.f);
                if (out) {
                    float2 v = make_float2(vx, vy);
                    *reinterpret_cast<float2*>(out + (size_t)r * DIMF + n) = v;
                }
                if (out16)
                    *reinterpret_cast<__half2*>(out16 + (size_t)r * DIMF + n) =
                        __floats2half2_rn(vx, vy);
            }
            if (r + 8 < N_NODES) {
                float vx = fmaxf(acc[mt][nt][2] + bv0, 0.f);
                float vy = fmaxf(acc[mt][nt][3] + bv1, 0.f);
                if (out) {
                    float2 v = make_float2(vx, vy);
                    *reinterpret_cast<float2*>(out + (size_t)(r + 8) * DIMF + n) = v;
                }
                if (out16)
                    *reinterpret_cast<__half2*>(out16 + (size_t)(r + 8) * DIMF + n) =
                        __floats2half2_rn(vx, vy);
            }
        }
    }
}

// ---------------------------------------------------------------------------
// launch
// ---------------------------------------------------------------------------
extern "C" void kernel_launch(void* const* d_in, const int* in_sizes, int n_in,
                              void* d_out, int out_size) {
    const float* x   = (const float*)d_in[0];
    const int*   ei  = (const int*)d_in[1];
    const float* W1l = (const float*)d_in[2];
    const float* b1l = (const float*)d_in[3];
    const float* W1r = (const float*)d_in[4];
    const float* W2l = (const float*)d_in[5];
    const float* b2l = (const float*)d_in[6];
    const float* W2r = (const float*)d_in[7];
    float* out = (float*)d_out;

    const int tot4      = N_NODES * DIMF / 4;
    const int prep_grid = (tot4 + 255) / 256;
    const int sort_grid = (N_EDGES / 4 + 255) / 256;      // 4 edges/thread
    const int agg_grid  = (N_NODES + 7) / 8;              // warp per node
    const int gemm_grid = (N_NODES + BM - 1) / BM;        // 313

    static __half* p_mh = nullptr;
    static __half* p_xh = nullptr;
    static __half* p_hh = nullptr;
    static __half* p_wh = nullptr;
    if (!p_mh) {
        cudaGetSymbolAddress((void**)&p_mh, g_mh);
        cudaGetSymbolAddress((void**)&p_xh, g_xh);
        cudaGetSymbolAddress((void**)&p_hh, g_hh);
        cudaGetSymbolAddress((void**)&p_wh, g_wh);
        cudaFuncSetAttribute(gemm_tc_kernel,
                             cudaFuncAttributeMaxDynamicSharedMemorySize, SMEM_BYTES);
    }
    const int WSZ = DIMF * DIMF;
    __half* w1l_h = p_wh;
    __half* w1r_h = p_wh + WSZ;
    __half* w2l_h = p_wh + 2 * WSZ;
    __half* w2r_h = p_wh + 3 * WSZ;

    // ---- prep (x shadow + weight cvt + cursor zero), then counting sort ----
    prep_kernel<<<prep_grid, 256>>>(x, W1l, W1r, W2l, W2r);
    sort_kernel<<<sort_grid, 256>>>(ei);

    // ---- layer 1 (only fp16 shadow needed) ----
    agg_kernel<<<agg_grid, 256>>>(p_xh);
    gemm_tc_kernel<<<gemm_grid, 256, SMEM_BYTES>>>(p_mh, p_xh, w1l_h, w1r_h,
                                                   b1l, nullptr, p_hh);

    // ---- layer 2 ----
    agg_kernel<<<agg_grid, 256>>>(p_hh);
    gemm_tc_kernel<<<gemm_grid, 256, SMEM_BYTES>>>(p_mh, p_hh, w2l_h, w2r_h,
                                                   b2l, out, nullptr);
}